// round 1
// baseline (speedup 1.0000x reference)
#include <cuda_runtime.h>

// ---------------------------------------------------------------------------
// FusionModel: out = head(bn2(leaky(bn1(leaky(kron(v1,v2,v3) @ W1 + b1)) @ W2 + b2)))
//
// Stage 1 (k_gemm):  H1pre[b,h] = sum_f x[b,f] * W1[f,h], split-K over slabs.
//   A K-slab (fixed i,j; k in [0,64)) of x is rank-1:
//     x[b, slab, k] = (v1e[b,i] * v2e[b,j]) * v3e[b,k]
//   so each block keeps a v3 tile in smem (loaded ONCE) and per slab only
//   loads a 64x64 W1 tile + 64 scalars. Inner product deferred-scales by s:
//     acc += s * (sum_k v3[b,k] * W[k,h]).
//   Uses packed fma.rn.f32x2 (sm_103a) for 2x fp32 FMA throughput.
// Stage 2 (k_epi):   bias + leaky + bn1 + layer2 + leaky + bn2 + head.
// ---------------------------------------------------------------------------

namespace {
constexpr int BATCH = 256;
constexpr int DIN   = 63;
constexpr int D1    = 64;
constexpr int H1    = 256;
constexpr int H2    = 128;
constexpr float EPSV  = 1e-5f;
constexpr float SLOPE = 0.1f;

constexpr int BM = 64;   // batch rows per block
constexpr int BN = 64;   // h1 cols per block
constexpr int BK = 64;   // one slab (k dimension of v3)
constexpr int NSLABS = D1 * D1;          // 4096
constexpr int SLABS_PER_BLOCK = 64;
constexpr int NCHUNK = NSLABS / SLABS_PER_BLOCK;  // 64
constexpr int NTHREADS = 256;
}

// split-K accumulator for H1 pre-activation
__device__ float g_acc[BATCH * H1];

__global__ void k_zero() {
    int i = blockIdx.x * blockDim.x + threadIdx.x;
    if (i < BATCH * H1) g_acc[i] = 0.0f;
}

// ---- packed f32x2 helpers (Blackwell) -------------------------------------
__device__ __forceinline__ unsigned long long pk2(float lo, float hi) {
    unsigned long long r;
    asm("mov.b64 %0, {%1, %2};" : "=l"(r) : "f"(lo), "f"(hi));
    return r;
}
__device__ __forceinline__ void fma2(unsigned long long& d,
                                     unsigned long long a,
                                     unsigned long long b) {
    asm("fma.rn.f32x2 %0, %1, %2, %0;" : "+l"(d) : "l"(a), "l"(b));
}
__device__ __forceinline__ float2 up2(unsigned long long v) {
    float2 f;
    asm("mov.b64 {%0, %1}, %2;" : "=f"(f.x), "=f"(f.y) : "l"(v));
    return f;
}

// ---------------------------------------------------------------------------
__global__ __launch_bounds__(NTHREADS)
void k_gemm(const float* __restrict__ v1,
            const float* __restrict__ v2,
            const float* __restrict__ v3,
            const float* __restrict__ W1) {
    __shared__ float V3s[BK][BM];   // [k][bb]  16 KB, loaded once per block
    __shared__ float Wt[BK][BN];    // [k][h]   16 KB, per slab
    __shared__ float Ssl[BM];       // s[bb] = v1e[b,i]*v2e[b,j], per slab

    const int tid   = threadIdx.x;
    const int bbase = blockIdx.x * BM;
    const int hbase = blockIdx.y * BN;
    const int slab0 = blockIdx.z * SLABS_PER_BLOCK;

    // fill v3 tile, k-major: V3s[k][bb] = v3e[bbase+bb][k]
    for (int idx = tid; idx < BK * BM; idx += NTHREADS) {
        int k = idx >> 6, bb = idx & 63;
        V3s[k][bb] = (k < DIN) ? v3[(bbase + bb) * DIN + k] : 1.0f;
    }

    const int tx = tid & 15;         // 16 col groups
    const int ty = tid >> 4;         // 16 row groups
    const int r0 = ty * 4;           // 4 rows / thread
    const int c0 = tx * 4;           // 4 cols / thread (2 f32x2 pairs)

    unsigned long long acc[4][2];
#pragma unroll
    for (int r = 0; r < 4; r++) { acc[r][0] = 0ull; acc[r][1] = 0ull; }

    for (int s = 0; s < SLABS_PER_BLOCK; ++s) {
        const int slab = slab0 + s;
        __syncthreads();  // protect Wt/Ssl from previous iteration readers

        // load W1 slab tile: rows f = slab*64 + k, cols hbase..hbase+63
        for (int i = tid; i < (BK * BN) / 4; i += NTHREADS) {
            int row  = i >> 4;
            int col4 = (i & 15) * 4;
            const float4 w = *reinterpret_cast<const float4*>(
                W1 + (size_t)(slab * 64 + row) * H1 + hbase + col4);
            *reinterpret_cast<float4*>(&Wt[row][col4]) = w;
        }
        if (tid < BM) {
            int b = bbase + tid;
            int i = slab >> 6, j = slab & 63;
            float a = (i < DIN) ? v1[b * DIN + i] : 1.0f;
            float c = (j < DIN) ? v2[b * DIN + j] : 1.0f;
            Ssl[tid] = a * c;
        }
        __syncthreads();

        unsigned long long t[4][2];
#pragma unroll
        for (int r = 0; r < 4; r++) { t[r][0] = 0ull; t[r][1] = 0ull; }

#pragma unroll 8
        for (int k = 0; k < BK; ++k) {
            const float4 av = *reinterpret_cast<const float4*>(&V3s[k][r0]);
            const float4 wv = *reinterpret_cast<const float4*>(&Wt[k][c0]);
            const unsigned long long w01 = pk2(wv.x, wv.y);
            const unsigned long long w23 = pk2(wv.z, wv.w);
            unsigned long long a;
            a = pk2(av.x, av.x); fma2(t[0][0], a, w01); fma2(t[0][1], a, w23);
            a = pk2(av.y, av.y); fma2(t[1][0], a, w01); fma2(t[1][1], a, w23);
            a = pk2(av.z, av.z); fma2(t[2][0], a, w01); fma2(t[2][1], a, w23);
            a = pk2(av.w, av.w); fma2(t[3][0], a, w01); fma2(t[3][1], a, w23);
        }

        // deferred scale: acc += s[b] * t
#pragma unroll
        for (int r = 0; r < 4; r++) {
            const float sv = Ssl[r0 + r];
            const unsigned long long ss = pk2(sv, sv);
            fma2(acc[r][0], ss, t[r][0]);
            fma2(acc[r][1], ss, t[r][1]);
        }
    }

    // split-K reduction into global accumulator
#pragma unroll
    for (int r = 0; r < 4; r++) {
        const int brow = bbase + r0 + r;
        const float2 p0 = up2(acc[r][0]);
        const float2 p1 = up2(acc[r][1]);
        float* dst = &g_acc[brow * H1 + hbase + c0];
        atomicAdd(dst + 0, p0.x);
        atomicAdd(dst + 1, p0.y);
        atomicAdd(dst + 2, p1.x);
        atomicAdd(dst + 3, p1.y);
    }
}

// ---------------------------------------------------------------------------
__global__ __launch_bounds__(H2)
void k_epi(const float* __restrict__ b1,  const float* __restrict__ g1,
           const float* __restrict__ be1, const float* __restrict__ rm1,
           const float* __restrict__ rv1, const float* __restrict__ W2,
           const float* __restrict__ b2,  const float* __restrict__ g2,
           const float* __restrict__ be2, const float* __restrict__ rm2,
           const float* __restrict__ rv2, const float* __restrict__ Wc,
           const float* __restrict__ bc,  float* __restrict__ out) {
    __shared__ float h1s[H1];
    __shared__ float red[H2];
    const int b = blockIdx.x;
    const int t = threadIdx.x;  // 128

    for (int h = t; h < H1; h += H2) {
        float x = g_acc[b * H1 + h] + b1[h];
        x = (x >= 0.0f) ? x : SLOPE * x;
        x = (x - rm1[h]) * rsqrtf(rv1[h] + EPSV) * g1[h] + be1[h];
        h1s[h] = x;
    }
    __syncthreads();

    float a = 0.0f;
#pragma unroll 8
    for (int i = 0; i < H1; i++) a += h1s[i] * W2[i * H2 + t];
    a += b2[t];
    a = (a >= 0.0f) ? a : SLOPE * a;
    a = (a - rm2[t]) * rsqrtf(rv2[t] + EPSV) * g2[t] + be2[t];
    red[t] = a * Wc[t];
    __syncthreads();

    for (int sft = H2 / 2; sft > 0; sft >>= 1) {
        if (t < sft) red[t] += red[t + sft];
        __syncthreads();
    }
    if (t == 0) out[b] = red[0] + bc[0];
}

// ---------------------------------------------------------------------------
extern "C" void kernel_launch(void* const* d_in, const int* in_sizes, int n_in,
                              void* d_out, int out_size) {
    const float* vec1  = (const float*)d_in[0];
    const float* vec2  = (const float*)d_in[1];
    const float* vec3  = (const float*)d_in[2];
    const float* W1    = (const float*)d_in[3];
    const float* b1    = (const float*)d_in[4];
    const float* g1    = (const float*)d_in[5];
    const float* beta1 = (const float*)d_in[6];
    const float* rm1   = (const float*)d_in[7];
    const float* rv1   = (const float*)d_in[8];
    const float* W2    = (const float*)d_in[9];
    const float* b2    = (const float*)d_in[10];
    const float* g2    = (const float*)d_in[11];
    const float* beta2 = (const float*)d_in[12];
    const float* rm2   = (const float*)d_in[13];
    const float* rv2   = (const float*)d_in[14];
    const float* Wc    = (const float*)d_in[15];
    const float* bc    = (const float*)d_in[16];
    float* out = (float*)d_out;

    k_zero<<<(BATCH * H1 + 1023) / 1024, 1024>>>();

    dim3 grid(BATCH / BM, H1 / BN, NCHUNK);  // (4, 4, 64)
    k_gemm<<<grid, NTHREADS>>>(vec1, vec2, vec3, W1);

    k_epi<<<BATCH, H2>>>(b1, g1, beta1, rm1, rv1, W2, b2, g2, beta2,
                         rm2, rv2, Wc, bc, out);
}

// round 3
// speedup vs baseline: 3.4645x; 3.4645x over previous
#include <cuda_runtime.h>
#include <cstdint>

// ===========================================================================
// FusionModel via portable tensor-core PTX (mma.sync tf32) — no sm_103a-only
// features (harness compiles at virtual compute_103).
//
//   H1pre = x @ W1,  x[b,(i*64+j)*64+k] = v1e[b,i]*v2e[b,j]*v3e[b,k]
//   M=256, N=256, K=262144. Grid: 2 M-tiles x 74 K-chunks = 148 CTAs.
//   Per slab (fixed i,j; K=64): A is rank-1, generated from smem-resident v3
//   + per-slab scalars; B = W1 slab streamed via cp.async (double-buffered,
//   swizzled for conflict-free fragment loads). Registers accumulate the
//   128x256 CTA tile; split-K reduced with atomicAdd into g_acc.
// ===========================================================================

namespace {
constexpr int BATCH = 256;
constexpr int DIN   = 63;
constexpr int H1    = 256;
constexpr int H2    = 128;
constexpr float EPSV  = 1e-5f;
constexpr float SLOPE = 0.1f;

constexpr int NSLABS  = 4096;
constexpr int NCHUNKS = 74;
constexpr int NT      = 256;

constexpr int SMB_BYTES = 65536;                 // one B slab: 64k x 256n fp32
constexpr int V3_STRIDE = 68;                    // padded row (floats)
constexpr int SM_B   = 0;                        // 2 x 64 KB
constexpr int SM_V3  = 2 * SMB_BYTES;            // 131072
constexpr int SM_S   = SM_V3 + 128 * V3_STRIDE * 4;   // 165888
constexpr int SM_TOTAL = SM_S + 2 * 128 * 4;     // 166912 bytes
}

__device__ float g_acc[BATCH * H1];

__global__ void k_zero() {
    int i = blockIdx.x * blockDim.x + threadIdx.x;
    if (i < BATCH * H1) g_acc[i] = 0.0f;
}

// ---- helpers --------------------------------------------------------------
__device__ __forceinline__ uint32_t smem_u32(const void* p) {
    uint32_t a;
    asm("{ .reg .u64 t; cvta.to.shared.u64 t, %1; cvt.u32.u64 %0, t; }"
        : "=r"(a) : "l"(p));
    return a;
}
__device__ __forceinline__ uint32_t f2tf(float x) {
    uint32_t r;
    asm("cvt.rna.tf32.f32 %0, %1;" : "=r"(r) : "f"(x));
    return r;
}
__device__ __forceinline__ void mma_tf32(float* c, const uint32_t* a,
                                         const uint32_t* b) {
    asm volatile(
        "mma.sync.aligned.m16n8k8.row.col.f32.tf32.tf32.f32 "
        "{%0,%1,%2,%3}, {%4,%5,%6,%7}, {%8,%9}, {%0,%1,%2,%3};"
        : "+f"(c[0]), "+f"(c[1]), "+f"(c[2]), "+f"(c[3])
        : "r"(a[0]), "r"(a[1]), "r"(a[2]), "r"(a[3]), "r"(b[0]), "r"(b[1]));
}
__device__ __forceinline__ void cp16(uint32_t dst, const void* src) {
    asm volatile("cp.async.cg.shared.global [%0], [%1], 16;"
                 :: "r"(dst), "l"(src));
}
#define CP_COMMIT() asm volatile("cp.async.commit_group;" ::: "memory")
#define CP_WAIT1()  asm volatile("cp.async.wait_group 1;" ::: "memory")

// swizzled float index of B[k][n] inside a slab buffer (k:0..63, n:0..255)
__device__ __forceinline__ int bidx(int k, int n) {
    return k * 256 + (((n >> 2) ^ ((k & 3) << 1)) << 2) + (n & 3);
}

// ---------------------------------------------------------------------------
__global__ __launch_bounds__(NT, 1)
void k_gemm_mma(const float* __restrict__ v1, const float* __restrict__ v2,
                const float* __restrict__ v3, const float* __restrict__ W1) {
    extern __shared__ char smem[];
    float* Bsm  = (float*)(smem + SM_B);          // [2][64*256] swizzled
    float* v3sm = (float*)(smem + SM_V3);         // [128][V3_STRIDE]
    float* ssm  = (float*)(smem + SM_S);          // [2][128]
    const uint32_t b_u32 = smem_u32(Bsm);

    const int tid = threadIdx.x;
    const int wid = tid >> 5, l = tid & 31;
    const int lq = l >> 2, lr = l & 3;
    const int wm = wid >> 2, wn = wid & 3;
    const int mr = wm * 64, nc = wn * 64;

    const int mtile = blockIdx.x;                 // 0..1
    const int chunk = blockIdx.y;                 // 0..73
    const int s_lo = (chunk * NSLABS) / NCHUNKS;
    const int s_hi = ((chunk + 1) * NSLABS) / NCHUNKS;

    // ---- v3 tile (once) ----
    for (int idx = tid; idx < 128 * 64; idx += NT) {
        int r = idx >> 6, c = idx & 63;
        v3sm[r * V3_STRIDE + c] =
            (c < DIN) ? v3[(mtile * 128 + r) * DIN + c] : 1.0f;
    }

    // ---- cp.async slab issue ----
    auto issue = [&](int s, int p) {
        const float* base = W1 + (size_t)s * 64 * H1;
        uint32_t bb = b_u32 + p * SMB_BYTES;
#pragma unroll
        for (int it = 0; it < 16; ++it) {
            int c = it * NT + tid;
            int k = c >> 6, cx = c & 63;
            uint32_t dst = bb + (uint32_t)((k * 64 + (cx ^ ((k & 3) << 1))) * 16);
            cp16(dst, base + (size_t)k * H1 + cx * 4);
        }
        CP_COMMIT();
    };

    issue(s_lo, 0);
    if (s_lo + 1 < s_hi) issue(s_lo + 1, 1);

    float acc[4][8][4];
#pragma unroll
    for (int mt = 0; mt < 4; ++mt)
#pragma unroll
        for (int nt = 0; nt < 8; ++nt)
#pragma unroll
            for (int q = 0; q < 4; ++q) acc[mt][nt][q] = 0.0f;

    for (int s = s_lo; s < s_hi; ++s) {
        const int sl = s - s_lo;
        const int p = sl & 1;
        const float* Bp = Bsm + p * (SMB_BYTES / 4);

        // per-slab row scalars s(b) = v1e[b,i]*v2e[b,j]
        if (tid < 128) {
            int b = mtile * 128 + tid;
            int i = s >> 6, j = s & 63;
            float ai = (i < DIN) ? __ldg(v1 + b * DIN + i) : 1.0f;
            float cj = (j < DIN) ? __ldg(v2 + b * DIN + j) : 1.0f;
            ssm[p * 128 + tid] = ai * cj;
        }
        CP_WAIT1();
        __syncthreads();

        // hoist row scalars for this warp's 4 m-tiles
        float sA[4][2];
#pragma unroll
        for (int mt = 0; mt < 4; ++mt) {
            int r = mr + mt * 16 + lq;
            sA[mt][0] = ssm[p * 128 + r];
            sA[mt][1] = ssm[p * 128 + r + 8];
        }

#pragma unroll
        for (int kk = 0; kk < 8; ++kk) {
            // A fragments: a = s(row) * v3(row, k)
            uint32_t a[4][4];
#pragma unroll
            for (int mt = 0; mt < 4; ++mt) {
                int r = mr + mt * 16 + lq;
                int c = kk * 8 + lr;
                float v00 = v3sm[r * V3_STRIDE + c];
                float v10 = v3sm[(r + 8) * V3_STRIDE + c];
                float v01 = v3sm[r * V3_STRIDE + c + 4];
                float v11 = v3sm[(r + 8) * V3_STRIDE + c + 4];
                a[mt][0] = f2tf(sA[mt][0] * v00);
                a[mt][1] = f2tf(sA[mt][1] * v10);
                a[mt][2] = f2tf(sA[mt][0] * v01);
                a[mt][3] = f2tf(sA[mt][1] * v11);
            }
            // B fragments (swizzled smem, conflict-free)
            uint32_t bfr[8][2];
#pragma unroll
            for (int nt = 0; nt < 8; ++nt) {
                int n  = nc + nt * 8 + lq;
                int k0 = kk * 8 + lr;
                bfr[nt][0] = f2tf(Bp[bidx(k0, n)]);
                bfr[nt][1] = f2tf(Bp[bidx(k0 + 4, n)]);
            }
#pragma unroll
            for (int mt = 0; mt < 4; ++mt)
#pragma unroll
                for (int nt = 0; nt < 8; ++nt)
                    mma_tf32(acc[mt][nt], a[mt], bfr[nt]);
        }
        __syncthreads();

        if (s + 2 < s_hi) issue(s + 2, p);
    }

    // ---- split-K reduction ----
#pragma unroll
    for (int mt = 0; mt < 4; ++mt) {
        const int row = mtile * 128 + mr + mt * 16 + lq;
#pragma unroll
        for (int nt = 0; nt < 8; ++nt) {
            const int col = nc + nt * 8 + lr * 2;
            atomicAdd(g_acc + row * H1 + col,           acc[mt][nt][0]);
            atomicAdd(g_acc + row * H1 + col + 1,       acc[mt][nt][1]);
            atomicAdd(g_acc + (row + 8) * H1 + col,     acc[mt][nt][2]);
            atomicAdd(g_acc + (row + 8) * H1 + col + 1, acc[mt][nt][3]);
        }
    }
}

// ---------------------------------------------------------------------------
__global__ __launch_bounds__(H2)
void k_epi(const float* __restrict__ b1,  const float* __restrict__ g1,
           const float* __restrict__ be1, const float* __restrict__ rm1,
           const float* __restrict__ rv1, const float* __restrict__ W2,
           const float* __restrict__ b2,  const float* __restrict__ g2,
           const float* __restrict__ be2, const float* __restrict__ rm2,
           const float* __restrict__ rv2, const float* __restrict__ Wc,
           const float* __restrict__ bc,  float* __restrict__ out) {
    __shared__ float h1s[H1];
    __shared__ float red[H2];
    const int b = blockIdx.x;
    const int t = threadIdx.x;

    for (int h = t; h < H1; h += H2) {
        float x = g_acc[b * H1 + h] + b1[h];
        x = (x >= 0.0f) ? x : SLOPE * x;
        x = (x - rm1[h]) * rsqrtf(rv1[h] + EPSV) * g1[h] + be1[h];
        h1s[h] = x;
    }
    __syncthreads();

    float a = 0.0f;
#pragma unroll 8
    for (int i = 0; i < H1; i++) a += h1s[i] * W2[i * H2 + t];
    a += b2[t];
    a = (a >= 0.0f) ? a : SLOPE * a;
    a = (a - rm2[t]) * rsqrtf(rv2[t] + EPSV) * g2[t] + be2[t];
    red[t] = a * Wc[t];
    __syncthreads();

    for (int sft = H2 / 2; sft > 0; sft >>= 1) {
        if (t < sft) red[t] += red[t + sft];
        __syncthreads();
    }
    if (t == 0) out[b] = red[0] + bc[0];
}

// ---------------------------------------------------------------------------
extern "C" void kernel_launch(void* const* d_in, const int* in_sizes, int n_in,
                              void* d_out, int out_size) {
    const float* vec1  = (const float*)d_in[0];
    const float* vec2  = (const float*)d_in[1];
    const float* vec3  = (const float*)d_in[2];
    const float* W1    = (const float*)d_in[3];
    const float* b1    = (const float*)d_in[4];
    const float* g1    = (const float*)d_in[5];
    const float* beta1 = (const float*)d_in[6];
    const float* rm1   = (const float*)d_in[7];
    const float* rv1   = (const float*)d_in[8];
    const float* W2    = (const float*)d_in[9];
    const float* b2    = (const float*)d_in[10];
    const float* g2    = (const float*)d_in[11];
    const float* beta2 = (const float*)d_in[12];
    const float* rm2   = (const float*)d_in[13];
    const float* rv2   = (const float*)d_in[14];
    const float* Wc    = (const float*)d_in[15];
    const float* bc    = (const float*)d_in[16];
    float* out = (float*)d_out;

    cudaFuncSetAttribute(k_gemm_mma,
                         cudaFuncAttributeMaxDynamicSharedMemorySize, SM_TOTAL);

    k_zero<<<(BATCH * H1 + 1023) / 1024, 1024>>>();

    dim3 grid(2, NCHUNKS);   // 148 CTAs
    k_gemm_mma<<<grid, NT, SM_TOTAL>>>(vec1, vec2, vec3, W1);

    k_epi<<<BATCH, H2>>>(b1, g1, beta1, rm1, rv1, W2, b2, g2, beta2,
                         rm2, rv2, Wc, bc, out);
}

// round 4
// speedup vs baseline: 5.0133x; 1.4470x over previous
#include <cuda_runtime.h>
#include <cstdint>

// ===========================================================================
// FusionModel via mma.sync m16n8k16 fp16 (2x MAC/op vs tf32; same 10-bit
// mantissa => comparable error). tcgen05 unavailable at compute_103.
//
//   H1pre = x @ W1,  x[b,(i*64+j)*64+k] = v1e[b,i]*v2e[b,j]*v3e[b,k]
//   M=256, N=256, K=262144. Grid: 2 M-tiles x 74 K-chunks = 148 CTAs.
//   Per slab: A (rank-1) computed into SMEM as fp16 from register-resident
//   v3 + per-slab scalar; B = W1 slab via cp.async (fp32, double-buffered,
//   swizzled), packed to fp16 at fragment-load time with RNE. 128x256 CTA
//   tile accumulated in fp32 registers; split-K atomicAdd into g_acc.
// ===========================================================================

namespace {
constexpr int BATCH = 256;
constexpr int DIN   = 63;
constexpr int H1    = 256;
constexpr int H2    = 128;
constexpr float EPSV  = 1e-5f;
constexpr float SLOPE = 0.1f;

constexpr int NSLABS  = 4096;
constexpr int NCHUNKS = 74;
constexpr int NT      = 256;

constexpr int SMB_BYTES = 65536;        // B slab: 64k x 256n fp32 (swizzled)
constexpr int SMA_BYTES = 128 * 144;    // A slab: 128 rows x (64 half + pad)
constexpr int SM_B   = 0;               // 2 x 64 KB
constexpr int SM_A   = 2 * SMB_BYTES;   // 131072, 2 x 18432
constexpr int SM_TOTAL = SM_A + 2 * SMA_BYTES;   // 167936 B
constexpr int A_WSTRIDE = 36;           // words per A row (144 B)
}

__device__ float g_acc[BATCH * H1];

__global__ void k_zero() {
    int i = blockIdx.x * blockDim.x + threadIdx.x;
    if (i < BATCH * H1) g_acc[i] = 0.0f;
}

// ---- helpers --------------------------------------------------------------
__device__ __forceinline__ uint32_t smem_u32(const void* p) {
    uint32_t a;
    asm("{ .reg .u64 t; cvta.to.shared.u64 t, %1; cvt.u32.u64 %0, t; }"
        : "=r"(a) : "l"(p));
    return a;
}
__device__ __forceinline__ uint32_t pkh2(float lo, float hi) {
    uint32_t d;  // d = {lo: cvt(lo), hi: cvt(hi)}; PTX operand order: d, hi, lo
    asm("cvt.rn.f16x2.f32 %0, %1, %2;" : "=r"(d) : "f"(hi), "f"(lo));
    return d;
}
__device__ __forceinline__ void mma_f16(float* c, const uint32_t* a,
                                        const uint32_t* b) {
    asm volatile(
        "mma.sync.aligned.m16n8k16.row.col.f32.f16.f16.f32 "
        "{%0,%1,%2,%3}, {%4,%5,%6,%7}, {%8,%9}, {%0,%1,%2,%3};"
        : "+f"(c[0]), "+f"(c[1]), "+f"(c[2]), "+f"(c[3])
        : "r"(a[0]), "r"(a[1]), "r"(a[2]), "r"(a[3]), "r"(b[0]), "r"(b[1]));
}
__device__ __forceinline__ void cp16(uint32_t dst, const void* src) {
    asm volatile("cp.async.cg.shared.global [%0], [%1], 16;"
                 :: "r"(dst), "l"(src));
}
#define CP_COMMIT() asm volatile("cp.async.commit_group;" ::: "memory")
#define CP_WAIT1()  asm volatile("cp.async.wait_group 1;" ::: "memory")

// swizzled float index of B[k][n] (k:0..63, n:0..255), xor class (k>>1)&3
__device__ __forceinline__ int bidx(int k, int n) {
    return k * 256 + (((n >> 2) ^ (((k >> 1) & 3) << 1)) << 2) + (n & 3);
}

// ---------------------------------------------------------------------------
__global__ __launch_bounds__(NT, 1)
void k_gemm_mma(const float* __restrict__ v1, const float* __restrict__ v2,
                const float* __restrict__ v3, const float* __restrict__ W1) {
    extern __shared__ char smem[];
    float*    Bsm = (float*)(smem + SM_B);
    uint32_t* Asm = (uint32_t*)(smem + SM_A);   // [2][128 rows][36 words]
    const uint32_t b_u32 = smem_u32(Bsm);

    const int tid = threadIdx.x;
    const int wid = tid >> 5, l = tid & 31;
    const int lq = l >> 2, lr = l & 3;
    const int wm = wid >> 2, wn = wid & 3;
    const int mr = wm * 64, nc = wn * 64;

    const int mtile = blockIdx.x;
    const int chunk = blockIdx.y;
    const int s_lo = (chunk * NSLABS) / NCHUNKS;
    const int s_hi = ((chunk + 1) * NSLABS) / NCHUNKS;

    // A-generation assignment: thread owns (row tb, k-half h); v3 in registers
    const int tb = tid >> 1;
    const int h  = tid & 1;
    const int bg = mtile * 128 + tb;
    float v3r[32];
#pragma unroll
    for (int q = 0; q < 32; ++q) {
        int kk = h * 32 + q;
        v3r[q] = (kk < DIN) ? v3[bg * DIN + kk] : 1.0f;
    }

    // ---- cp.async B slab issue ----
    auto issue = [&](int s, int p) {
        const float* base = W1 + (size_t)s * 64 * H1;
        uint32_t bb = b_u32 + p * SMB_BYTES;
#pragma unroll
        for (int it = 0; it < 16; ++it) {
            int c = it * NT + tid;
            int k = c >> 6, cx = c & 63;
            uint32_t dst = bb + (uint32_t)((k * 64 + (cx ^ (((k >> 1) & 3) << 1))) * 16);
            cp16(dst, base + (size_t)k * H1 + cx * 4);
        }
        CP_COMMIT();
    };

    issue(s_lo, 0);
    if (s_lo + 1 < s_hi) issue(s_lo + 1, 1);

    float acc[4][8][4];
#pragma unroll
    for (int mt = 0; mt < 4; ++mt)
#pragma unroll
        for (int nt = 0; nt < 8; ++nt)
#pragma unroll
            for (int q = 0; q < 4; ++q) acc[mt][nt][q] = 0.0f;

    for (int s = s_lo; s < s_hi; ++s) {
        const int sl = s - s_lo;
        const int p = sl & 1;
        const float*    Bp = Bsm + p * (SMB_BYTES / 4);
        const uint32_t* Ap = Asm + p * (SMA_BYTES / 4);

        // ---- A gen: fp16 A[row][k] = cvt(s(b) * v3[b,k]) ----
        {
            int i = s >> 6, j = s & 63;
            float ai = (i < DIN) ? __ldg(v1 + bg * DIN + i) : 1.0f;
            float cj = (j < DIN) ? __ldg(v2 + bg * DIN + j) : 1.0f;
            float sv = ai * cj;
            uint32_t* dst = (uint32_t*)(smem + SM_A + p * SMA_BYTES) +
                            tb * A_WSTRIDE + h * 16;
#pragma unroll
            for (int g = 0; g < 4; ++g) {
                uint4 v;
                v.x = pkh2(sv * v3r[g * 8 + 0], sv * v3r[g * 8 + 1]);
                v.y = pkh2(sv * v3r[g * 8 + 2], sv * v3r[g * 8 + 3]);
                v.z = pkh2(sv * v3r[g * 8 + 4], sv * v3r[g * 8 + 5]);
                v.w = pkh2(sv * v3r[g * 8 + 6], sv * v3r[g * 8 + 7]);
                *(uint4*)(dst + g * 4) = v;
            }
        }

        CP_WAIT1();
        __syncthreads();

#pragma unroll
        for (int kk = 0; kk < 4; ++kk) {
            const int kw = kk * 8 + lr;     // word offset within A row
            const int kb = kk * 16;         // k base for B
            // A fragments (conflict-free LDS.32 half2)
            uint32_t a[4][4];
#pragma unroll
            for (int mt = 0; mt < 4; ++mt) {
                const uint32_t* ar = Ap + (mr + mt * 16 + lq) * A_WSTRIDE;
                a[mt][0] = ar[kw];
                a[mt][1] = ar[8 * A_WSTRIDE + kw];
                a[mt][2] = ar[kw + 4];
                a[mt][3] = ar[8 * A_WSTRIDE + kw + 4];
            }
            // B fragments (fp32 loads, RNE pack to fp16)
            const int k0 = kb + lr * 2;
            uint32_t bfr[8][2];
#pragma unroll
            for (int nt = 0; nt < 8; ++nt) {
                const int n = nc + nt * 8 + lq;
                bfr[nt][0] = pkh2(Bp[bidx(k0, n)],     Bp[bidx(k0 + 1, n)]);
                bfr[nt][1] = pkh2(Bp[bidx(k0 + 8, n)], Bp[bidx(k0 + 9, n)]);
            }
#pragma unroll
            for (int mt = 0; mt < 4; ++mt)
#pragma unroll
                for (int nt = 0; nt < 8; ++nt)
                    mma_f16(acc[mt][nt], a[mt], bfr[nt]);
        }
        __syncthreads();

        if (s + 2 < s_hi) issue(s + 2, p);
    }

    // ---- split-K reduction ----
#pragma unroll
    for (int mt = 0; mt < 4; ++mt) {
        const int row = mtile * 128 + mr + mt * 16 + lq;
#pragma unroll
        for (int nt = 0; nt < 8; ++nt) {
            const int col = nc + nt * 8 + lr * 2;
            atomicAdd(g_acc + row * H1 + col,           acc[mt][nt][0]);
            atomicAdd(g_acc + row * H1 + col + 1,       acc[mt][nt][1]);
            atomicAdd(g_acc + (row + 8) * H1 + col,     acc[mt][nt][2]);
            atomicAdd(g_acc + (row + 8) * H1 + col + 1, acc[mt][nt][3]);
        }
    }
}

// ---------------------------------------------------------------------------
__global__ __launch_bounds__(H2)
void k_epi(const float* __restrict__ b1,  const float* __restrict__ g1,
           const float* __restrict__ be1, const float* __restrict__ rm1,
           const float* __restrict__ rv1, const float* __restrict__ W2,
           const float* __restrict__ b2,  const float* __restrict__ g2,
           const float* __restrict__ be2, const float* __restrict__ rm2,
           const float* __restrict__ rv2, const float* __restrict__ Wc,
           const float* __restrict__ bc,  float* __restrict__ out) {
    __shared__ float h1s[H1];
    __shared__ float red[H2];
    const int b = blockIdx.x;
    const int t = threadIdx.x;

    for (int hh = t; hh < H1; hh += H2) {
        float x = g_acc[b * H1 + hh] + b1[hh];
        x = (x >= 0.0f) ? x : SLOPE * x;
        x = (x - rm1[hh]) * rsqrtf(rv1[hh] + EPSV) * g1[hh] + be1[hh];
        h1s[hh] = x;
    }
    __syncthreads();

    float a = 0.0f;
#pragma unroll 8
    for (int i = 0; i < H1; i++) a += h1s[i] * W2[i * H2 + t];
    a += b2[t];
    a = (a >= 0.0f) ? a : SLOPE * a;
    a = (a - rm2[t]) * rsqrtf(rv2[t] + EPSV) * g2[t] + be2[t];
    red[t] = a * Wc[t];
    __syncthreads();

    for (int sft = H2 / 2; sft > 0; sft >>= 1) {
        if (t < sft) red[t] += red[t + sft];
        __syncthreads();
    }
    if (t == 0) out[b] = red[0] + bc[0];
}

// ---------------------------------------------------------------------------
extern "C" void kernel_launch(void* const* d_in, const int* in_sizes, int n_in,
                              void* d_out, int out_size) {
    const float* vec1  = (const float*)d_in[0];
    const float* vec2  = (const float*)d_in[1];
    const float* vec3  = (const float*)d_in[2];
    const float* W1    = (const float*)d_in[3];
    const float* b1    = (const float*)d_in[4];
    const float* g1    = (const float*)d_in[5];
    const float* beta1 = (const float*)d_in[6];
    const float* rm1   = (const float*)d_in[7];
    const float* rv1   = (const float*)d_in[8];
    const float* W2    = (const float*)d_in[9];
    const float* b2    = (const float*)d_in[10];
    const float* g2    = (const float*)d_in[11];
    const float* beta2 = (const float*)d_in[12];
    const float* rm2   = (const float*)d_in[13];
    const float* rv2   = (const float*)d_in[14];
    const float* Wc    = (const float*)d_in[15];
    const float* bc    = (const float*)d_in[16];
    float* out = (float*)d_out;

    cudaFuncSetAttribute(k_gemm_mma,
                         cudaFuncAttributeMaxDynamicSharedMemorySize, SM_TOTAL);

    k_zero<<<(BATCH * H1 + 1023) / 1024, 1024>>>();

    dim3 grid(2, NCHUNKS);   // 148 CTAs
    k_gemm_mma<<<grid, NT, SM_TOTAL>>>(vec1, vec2, vec3, W1);

    k_epi<<<BATCH, H2>>>(b1, g1, beta1, rm1, rv1, W2, b2, g2, beta2,
                         rm2, rv2, Wc, bc, out);
}